// round 4
// baseline (speedup 1.0000x reference)
#include <cuda_runtime.h>
#include <math_constants.h>

// DilateErode tropical matmul, unified max-plus:
//   dilated[b,n] = max_f ( xb[b,f] + D[f,n] )
//   eroded [b,n] = -max_f( (-xb[b,f]) + E[f,n] )   (bit-exact vs fp32 ref)
//
// No swizzle: loader thread-mapping makes linear smem layout conflict-free
// (STS.128 wavefront = 8 consecutive rows). All inner-loop smem addresses are
// base + compile-time immediate. Double buffer, 1 barrier/tile, LDG prefetch.

#define Fdim 1024
#define Bdim 1024
#define NW   256
#define OUTC 512
#define BM   64
#define BN   64
#define KB   32
#define NT   (Fdim / KB)   // 32
#define QG   (KB / 4)      // 8 groups of 4 k

__global__ __launch_bounds__(256, 1)
void trop_kernel(const float* __restrict__ x,
                 const float* __restrict__ dil,
                 const float* __restrict__ ero,
                 float* __restrict__ out)
{
    // xsT[buf][q][row] : float4 = sign-applied x[row, k0+4q .. 4q+3]  (linear!)
    // ws [buf][k][c4]  : float4 = W[k0+k, wColBase+4*c4 .. +3]
    __shared__ float4 xsT[2][QG][BM];      // 16 KB
    __shared__ float4 ws [2][KB][BN / 4];  // 16 KB

    const int tid = threadIdx.x;
    const int tx  = tid & 15;          // 4 output cols
    const int ty  = tid >> 4;          // 4 output rows
    const int rowBase = blockIdx.y * BM;

    const bool erode     = (blockIdx.x < 4);
    const unsigned smask = erode ? 0x80000000u : 0u;
    const float* __restrict__ W = erode ? ero : dil;
    const int wColBase   = (blockIdx.x & 3) * BN;
    const int outColBase = blockIdx.x * BN;

    // x loader: row_lo = tid&7, q = (tid>>3)&7, row_hi = tid>>6
    //   -> STS wavefront (8 lanes) = 8 consecutive rows, contiguous 128B.
    const int xq   = (tid >> 3) & 7;
    const int xrow = ((tid >> 6) << 3) | (tid & 7);   // 0..31 (+32 for 2nd)
    const float4* xp = (const float4*)(x + (size_t)(rowBase + xrow) * Fdim) + xq;
    const int xstride4 = 32 * (Fdim / 4);

    // w loader: k = tid>>4 (+16), c4 = tid&15 -> contiguous per wavefront.
    const int wc4 = tid & 15;
    const int wk0 = tid >> 4;
    const float4* wp = (const float4*)(W + (size_t)wk0 * NW + wColBase) + wc4;
    const int wstride4 = 16 * (NW / 4);

    // prefetch tile 0
    float4 xr0 = xp[0];
    float4 xr1 = xp[xstride4];
    float4 wr0 = wp[0];
    float4 wr1 = wp[wstride4];

    float acc[4][4];
#pragma unroll
    for (int i = 0; i < 4; ++i)
#pragma unroll
        for (int j = 0; j < 4; ++j)
            acc[i][j] = -CUDART_INF_F;

#pragma unroll 2
    for (int t = 0; t < NT; ++t) {
        const int buf = t & 1;

        // ---- store prefetched tile (x sign-flipped via LOP3) ----
        {
            uint4 u0 = *(uint4*)&xr0, u1 = *(uint4*)&xr1;
            u0.x ^= smask; u0.y ^= smask; u0.z ^= smask; u0.w ^= smask;
            u1.x ^= smask; u1.y ^= smask; u1.z ^= smask; u1.w ^= smask;
            xsT[buf][xq][xrow     ] = *(float4*)&u0;
            xsT[buf][xq][xrow + 32] = *(float4*)&u1;
            ws[buf][wk0     ][wc4] = wr0;
            ws[buf][wk0 + 16][wc4] = wr1;
        }

        // ---- prefetch next tile (hidden under compute) ----
        if (t + 1 < NT) {
            xp += KB / 4;
            wp += KB * (NW / 4);
            xr0 = xp[0];
            xr1 = xp[xstride4];
            wr0 = wp[0];
            wr1 = wp[wstride4];
        }
        __syncthreads();   // single barrier/tile; double buffer makes it safe

        // ---- compute: all smem offsets are compile-time immediates ----
#pragma unroll
        for (int q = 0; q < QG; ++q) {
            float4 xa[4];
#pragma unroll
            for (int i = 0; i < 4; ++i)
                xa[i] = xsT[buf][q][ty * 4 + i];   // broadcast, conflict-free

#pragma unroll
            for (int d = 0; d < 4; ++d) {
                float4 wv = ws[buf][q * 4 + d][tx];
                float wa[4] = {wv.x, wv.y, wv.z, wv.w};
                float xv[4];
                xv[0] = (d == 0) ? xa[0].x : (d == 1) ? xa[0].y : (d == 2) ? xa[0].z : xa[0].w;
                xv[1] = (d == 0) ? xa[1].x : (d == 1) ? xa[1].y : (d == 2) ? xa[1].z : xa[1].w;
                xv[2] = (d == 0) ? xa[2].x : (d == 1) ? xa[2].y : (d == 2) ? xa[2].z : xa[2].w;
                xv[3] = (d == 0) ? xa[3].x : (d == 1) ? xa[3].y : (d == 2) ? xa[3].z : xa[3].w;
#pragma unroll
                for (int i = 0; i < 4; ++i)
#pragma unroll
                    for (int j = 0; j < 4; ++j)
                        acc[i][j] = fmaxf(acc[i][j], xv[i] + wa[j]);
            }
        }
    }

    // ---- bias feature f = 1024 (xb contribution is 0) ----
    {
        float4 wb = *(const float4*)&W[(size_t)Fdim * NW + wColBase + (tx << 2)];
        float wa[4] = {wb.x, wb.y, wb.z, wb.w};
#pragma unroll
        for (int i = 0; i < 4; ++i)
#pragma unroll
            for (int j = 0; j < 4; ++j)
                acc[i][j] = fmaxf(acc[i][j], wa[j]);
    }

    // ---- store, undoing the sign flip for the erosion half ----
#pragma unroll
    for (int i = 0; i < 4; ++i) {
        int row = rowBase + ty * 4 + i;
        uint4 o;
        o.x = __float_as_uint(acc[i][0]) ^ smask;
        o.y = __float_as_uint(acc[i][1]) ^ smask;
        o.z = __float_as_uint(acc[i][2]) ^ smask;
        o.w = __float_as_uint(acc[i][3]) ^ smask;
        *(uint4*)&out[(size_t)row * OUTC + outColBase + (tx << 2)] = o;
    }
}

extern "C" void kernel_launch(void* const* d_in, const int* in_sizes, int n_in,
                              void* d_out, int out_size)
{
    const float* x   = (const float*)d_in[0];   // (1024, 1024)
    const float* dil = (const float*)d_in[1];   // (1025, 256)
    const float* ero = (const float*)d_in[2];   // (1025, 256)
    float* out = (float*)d_out;                 // (1024, 512) = [eroded | dilated]

    dim3 grid(OUTC / BN, Bdim / BM);            // (8, 16) = 128 blocks
    trop_kernel<<<grid, 256>>>(x, dil, ero, out);
}

// round 7
// speedup vs baseline: 4.4112x; 4.4112x over previous
#include <cuda_runtime.h>
#include <math_constants.h>

// DilateErode via candidate pruning.
//   dilated[b,n] = max_k ( xb_k + D[k,n] ),  eroded[b,n] = min_k ( xb_k - E[k,n] )
// with xb = [x, 0]. Since weight spread is tiny (~0.14), only k with
//   xb_k >= rowMax(xb) - (maxD - minD)   (dilation)
//   xb_k <= rowMin(xb) + (maxE - minE)   (erosion)
// can ever win -> ~1-4 candidates per row. Exact (same fp32 ops, exact max/min),
// with a full-scan fallback if a row exceeds CMAX candidates.

#define B     1024
#define Fdim  1024
#define NW    256
#define OUTC  512
#define KTOT  (Fdim + 1)        // 1025
#define WELEM (KTOT * NW)       // 262400
#define WE4   (WELEM / 4)       // 65600
#define NB1   128               // K1 blocks
#define CMAX  128

__device__ float4 g_part[NB1];           // {maxD, minD, maxE, minE} per block
__device__ int    g_cntD[B], g_cntE[B];
__device__ int    g_idxD[B * CMAX], g_idxE[B * CMAX];
__device__ float  g_valD[B * CMAX], g_valE[B * CMAX];

// ---------------- K1: weight extremes (per-block partials) ----------------
__global__ __launch_bounds__(256)
void k_wext(const float* __restrict__ D, const float* __restrict__ E)
{
    float maxD = -CUDART_INF_F, minD = CUDART_INF_F;
    float maxE = -CUDART_INF_F, minE = CUDART_INF_F;
    for (int i = blockIdx.x * blockDim.x + threadIdx.x; i < WE4;
         i += gridDim.x * blockDim.x) {
        float4 d = ((const float4*)D)[i];
        float4 e = ((const float4*)E)[i];
        maxD = fmaxf(maxD, fmaxf(fmaxf(d.x, d.y), fmaxf(d.z, d.w)));
        minD = fminf(minD, fminf(fminf(d.x, d.y), fminf(d.z, d.w)));
        maxE = fmaxf(maxE, fmaxf(fmaxf(e.x, e.y), fmaxf(e.z, e.w)));
        minE = fminf(minE, fminf(fminf(e.x, e.y), fminf(e.z, e.w)));
    }
#pragma unroll
    for (int off = 16; off; off >>= 1) {
        maxD = fmaxf(maxD, __shfl_xor_sync(0xffffffffu, maxD, off));
        minD = fminf(minD, __shfl_xor_sync(0xffffffffu, minD, off));
        maxE = fmaxf(maxE, __shfl_xor_sync(0xffffffffu, maxE, off));
        minE = fminf(minE, __shfl_xor_sync(0xffffffffu, minE, off));
    }
    __shared__ float4 s[8];
    int wid = threadIdx.x >> 5, lane = threadIdx.x & 31;
    if (lane == 0) s[wid] = make_float4(maxD, minD, maxE, minE);
    __syncthreads();
    if (threadIdx.x == 0) {
        float4 r = s[0];
#pragma unroll
        for (int w = 1; w < 8; ++w) {
            r.x = fmaxf(r.x, s[w].x); r.y = fminf(r.y, s[w].y);
            r.z = fmaxf(r.z, s[w].z); r.w = fminf(r.w, s[w].w);
        }
        g_part[blockIdx.x] = r;
    }
}

// ---------------- K2: row extremes + candidate lists ----------------
__global__ __launch_bounds__(256)
void k_rows(const float* __restrict__ x)
{
    const int b = blockIdx.x, tid = threadIdx.x;
    float4 v = ((const float4*)(x + (size_t)b * Fdim))[tid];
    float mx = fmaxf(fmaxf(v.x, v.y), fmaxf(v.z, v.w));
    float mn = fminf(fminf(v.x, v.y), fminf(v.z, v.w));
#pragma unroll
    for (int off = 16; off; off >>= 1) {
        mx = fmaxf(mx, __shfl_xor_sync(0xffffffffu, mx, off));
        mn = fminf(mn, __shfl_xor_sync(0xffffffffu, mn, off));
    }
    __shared__ float smx[8], smn[8];
    __shared__ float s_tauD, s_tauE;
    __shared__ int cD, cE;
    int wid = tid >> 5, lane = tid & 31;
    if (lane == 0) { smx[wid] = mx; smn[wid] = mn; }
    __syncthreads();
    if (tid == 0) {
        float MX = 0.0f, MN = 0.0f;   // bias feature xb=0 included
#pragma unroll
        for (int w = 0; w < 8; ++w) {
            MX = fmaxf(MX, smx[w]);
            MN = fminf(MN, smn[w]);
        }
        float maxD = -CUDART_INF_F, minD = CUDART_INF_F;
        float maxE = -CUDART_INF_F, minE = CUDART_INF_F;
        for (int i = 0; i < NB1; ++i) {
            float4 p = g_part[i];
            maxD = fmaxf(maxD, p.x); minD = fminf(minD, p.y);
            maxE = fmaxf(maxE, p.z); minE = fminf(minE, p.w);
        }
        float sprD = (maxD - minD) * 1.001f + 1e-6f;
        float sprE = (maxE - minE) * 1.001f + 1e-6f;
        s_tauD = MX - sprD;      // dilation candidates: xb_k >= tauD
        s_tauE = MN + sprE;      // erosion  candidates: xb_k <= tauE
        cD = 0; cE = 0;
    }
    __syncthreads();
    const float tauD = s_tauD, tauE = s_tauE;
    float vv[4] = {v.x, v.y, v.z, v.w};
#pragma unroll
    for (int d = 0; d < 4; ++d) {
        int k = tid * 4 + d;
        float xv = vv[d];
        if (xv >= tauD) {
            int p = atomicAdd(&cD, 1);
            if (p < CMAX) { g_idxD[b * CMAX + p] = k; g_valD[b * CMAX + p] = xv; }
        }
        if (xv <= tauE) {
            int p = atomicAdd(&cE, 1);
            if (p < CMAX) { g_idxE[b * CMAX + p] = k; g_valE[b * CMAX + p] = xv; }
        }
    }
    if (tid == 0) {               // bias feature k = 1024, value 0
        if (0.0f >= tauD) {
            int p = atomicAdd(&cD, 1);
            if (p < CMAX) { g_idxD[b * CMAX + p] = Fdim; g_valD[b * CMAX + p] = 0.0f; }
        }
        if (0.0f <= tauE) {
            int p = atomicAdd(&cE, 1);
            if (p < CMAX) { g_idxE[b * CMAX + p] = Fdim; g_valE[b * CMAX + p] = 0.0f; }
        }
    }
    __syncthreads();
    if (tid == 0) { g_cntD[b] = cD; g_cntE[b] = cE; }
}

// ---------------- K3: outputs from candidates ----------------
__global__ __launch_bounds__(256)
void k_out(const float* __restrict__ x,
           const float* __restrict__ D,
           const float* __restrict__ E,
           float* __restrict__ out)
{
    const int b = blockIdx.x, j = threadIdx.x;   // j = column 0..255
    __shared__ int   sIdxD[CMAX], sIdxE[CMAX];
    __shared__ float sValD[CMAX], sValE[CMAX];

    const int cD = g_cntD[b], cE = g_cntE[b];
    const bool fullD = (cD > CMAX), fullE = (cE > CMAX);
    const int nD = fullD ? 0 : cD;
    const int nE = fullE ? 0 : cE;

    if (j < nD) { sIdxD[j] = g_idxD[b * CMAX + j]; sValD[j] = g_valD[b * CMAX + j]; }
    if (j < nE) { sIdxE[j] = g_idxE[b * CMAX + j]; sValE[j] = g_valE[b * CMAX + j]; }
    __syncthreads();

    float accD = -CUDART_INF_F;
    float accE =  CUDART_INF_F;
    for (int i = 0; i < nD; ++i) {
        int k = sIdxD[i];
        accD = fmaxf(accD, sValD[i] + D[(size_t)k * NW + j]);
    }
    for (int i = 0; i < nE; ++i) {
        int k = sIdxE[i];
        accE = fminf(accE, sValE[i] - E[(size_t)k * NW + j]);
    }

    if (fullD) {    // exact fallback (never taken for the given data)
        for (int k = 0; k < Fdim; ++k)
            accD = fmaxf(accD, x[(size_t)b * Fdim + k] + D[(size_t)k * NW + j]);
        accD = fmaxf(accD, D[(size_t)Fdim * NW + j]);
    }
    if (fullE) {
        for (int k = 0; k < Fdim; ++k)
            accE = fminf(accE, x[(size_t)b * Fdim + k] - E[(size_t)k * NW + j]);
        accE = fminf(accE, -E[(size_t)Fdim * NW + j]);
    }

    out[(size_t)b * OUTC + j]      = accE;   // eroded
    out[(size_t)b * OUTC + NW + j] = accD;   // dilated
}

extern "C" void kernel_launch(void* const* d_in, const int* in_sizes, int n_in,
                              void* d_out, int out_size)
{
    const float* x   = (const float*)d_in[0];   // (1024, 1024)
    const float* dil = (const float*)d_in[1];   // (1025, 256)
    const float* ero = (const float*)d_in[2];   // (1025, 256)
    float* out = (float*)d_out;                 // (1024, 512) = [eroded | dilated]

    k_wext<<<NB1, 256>>>(dil, ero);
    k_rows<<<B, 256>>>(x);
    k_out<<<B, 256>>>(x, dil, ero, out);
}

// round 10
// speedup vs baseline: 7.3750x; 1.6719x over previous
#include <cuda_runtime.h>
#include <math_constants.h>

// DilateErode via candidate pruning (exact).
//   dilated[b,n] = max_k ( xb_k + D[k,n] ),  eroded[b,n] = min_k ( xb_k - E[k,n] )
// xb = [x, 0]. Only k with xb_k >= rowMax - (maxD-minD)  (dilation) or
// xb_k <= rowMin + (maxE-minE)  (erosion) can win -> ~1-4 candidates/row.
// K1: weight extremes (512-block partials).  K2: fused per-row kernel:
// row extremes + thresholds + smem candidate list + gathered output.
// Exact: the candidate set provably contains every argmax/argmin (padded
// bound), and fp max/min over any superset in any order is bit-identical.
// Full-scan fallback if a row ever exceeds CMAX candidates.

#define B     1024
#define Fdim  1024
#define NW    256
#define OUTC  512
#define WE4   ((Fdim + 1) * NW / 4)   // 65600 float4 per weight matrix
#define NB1   512
#define CMAX  64

__device__ float4 g_part[NB1];   // {maxD, minD, maxE, minE} per K1 block

// ---------------- K1: weight extremes, one pass, MLP=2 ----------------
__global__ __launch_bounds__(256)
void k_wext(const float* __restrict__ D, const float* __restrict__ E)
{
    const int i = blockIdx.x * 256 + threadIdx.x;
    float maxD = -CUDART_INF_F, minD = CUDART_INF_F;
    float maxE = -CUDART_INF_F, minE = CUDART_INF_F;
    if (i < WE4) {
        float4 d = ((const float4*)D)[i];
        float4 e = ((const float4*)E)[i];
        maxD = fmaxf(fmaxf(d.x, d.y), fmaxf(d.z, d.w));
        minD = fminf(fminf(d.x, d.y), fminf(d.z, d.w));
        maxE = fmaxf(fmaxf(e.x, e.y), fmaxf(e.z, e.w));
        minE = fminf(fminf(e.x, e.y), fminf(e.z, e.w));
    }
#pragma unroll
    for (int off = 16; off; off >>= 1) {
        maxD = fmaxf(maxD, __shfl_xor_sync(0xffffffffu, maxD, off));
        minD = fminf(minD, __shfl_xor_sync(0xffffffffu, minD, off));
        maxE = fmaxf(maxE, __shfl_xor_sync(0xffffffffu, maxE, off));
        minE = fminf(minE, __shfl_xor_sync(0xffffffffu, minE, off));
    }
    __shared__ float4 s[8];
    const int wid = threadIdx.x >> 5, lane = threadIdx.x & 31;
    if (lane == 0) s[wid] = make_float4(maxD, minD, maxE, minE);
    __syncthreads();
    if (wid == 0) {                       // warp 0: parallel fold of 8 partials
        float4 r = s[lane & 7];
        float a = r.x, bm = r.y, c = r.z, dm = r.w;
#pragma unroll
        for (int off = 4; off; off >>= 1) {
            a  = fmaxf(a,  __shfl_xor_sync(0xffffffffu, a,  off));
            bm = fminf(bm, __shfl_xor_sync(0xffffffffu, bm, off));
            c  = fmaxf(c,  __shfl_xor_sync(0xffffffffu, c,  off));
            dm = fminf(dm, __shfl_xor_sync(0xffffffffu, dm, off));
        }
        if (lane == 0) g_part[blockIdx.x] = make_float4(a, bm, c, dm);
    }
}

// ------------- K2: fused row extremes + candidates + output -------------
__global__ __launch_bounds__(256)
void k_fused(const float* __restrict__ x,
             const float* __restrict__ D,
             const float* __restrict__ E,
             float* __restrict__ out)
{
    const int b = blockIdx.x, tid = threadIdx.x;
    const int wid = tid >> 5, lane = tid & 31;

    __shared__ float sx[Fdim];                 // x row (for fallback)
    __shared__ float red[6][8];                // per-warp partials
    __shared__ float s_tauD, s_tauE;
    __shared__ int   cD, cE;
    __shared__ int   sIdxD[CMAX], sIdxE[CMAX];
    __shared__ float sValD[CMAX], sValE[CMAX];

    // issue all 3 independent global loads up front (MLP = 3)
    float4 v  = ((const float4*)(x + (size_t)b * Fdim))[tid];
    float4 p0 = g_part[tid];
    float4 p1 = g_part[tid + 256];

    ((float4*)sx)[tid] = v;
    if (tid == 0) { cD = 0; cE = 0; }

    float maxD = fmaxf(p0.x, p1.x), minD = fminf(p0.y, p1.y);
    float maxE = fmaxf(p0.z, p1.z), minE = fminf(p0.w, p1.w);
    float mx = fmaxf(fmaxf(v.x, v.y), fmaxf(v.z, v.w));
    float mn = fminf(fminf(v.x, v.y), fminf(v.z, v.w));

#pragma unroll
    for (int off = 16; off; off >>= 1) {
        mx   = fmaxf(mx,   __shfl_xor_sync(0xffffffffu, mx,   off));
        mn   = fminf(mn,   __shfl_xor_sync(0xffffffffu, mn,   off));
        maxD = fmaxf(maxD, __shfl_xor_sync(0xffffffffu, maxD, off));
        minD = fminf(minD, __shfl_xor_sync(0xffffffffu, minD, off));
        maxE = fmaxf(maxE, __shfl_xor_sync(0xffffffffu, maxE, off));
        minE = fminf(minE, __shfl_xor_sync(0xffffffffu, minE, off));
    }
    if (lane == 0) {
        red[0][wid] = mx;   red[1][wid] = mn;
        red[2][wid] = maxD; red[3][wid] = minD;
        red[4][wid] = maxE; red[5][wid] = minE;
    }
    __syncthreads();
    if (tid == 0) {
        float MX = 0.0f, MN = 0.0f;      // bias feature xb = 0 included
        float MD = -CUDART_INF_F, mD = CUDART_INF_F;
        float ME = -CUDART_INF_F, mE = CUDART_INF_F;
#pragma unroll
        for (int w = 0; w < 8; ++w) {
            MX = fmaxf(MX, red[0][w]); MN = fminf(MN, red[1][w]);
            MD = fmaxf(MD, red[2][w]); mD = fminf(mD, red[3][w]);
            ME = fmaxf(ME, red[4][w]); mE = fminf(mE, red[5][w]);
        }
        s_tauD = MX - ((MD - mD) * 1.001f + 1e-6f);
        s_tauE = MN + ((ME - mE) * 1.001f + 1e-6f);
    }
    __syncthreads();

    // ---- candidate build (smem only) ----
    const float tauD = s_tauD, tauE = s_tauE;
    float vv[4] = {v.x, v.y, v.z, v.w};
#pragma unroll
    for (int d = 0; d < 4; ++d) {
        const int k = tid * 4 + d;
        const float xv = vv[d];
        if (xv >= tauD) {
            int p = atomicAdd(&cD, 1);
            if (p < CMAX) { sIdxD[p] = k; sValD[p] = xv; }
        }
        if (xv <= tauE) {
            int p = atomicAdd(&cE, 1);
            if (p < CMAX) { sIdxE[p] = k; sValE[p] = xv; }
        }
    }
    if (tid == 0) {                      // bias feature k = Fdim, value 0
        if (0.0f >= tauD) {
            int p = atomicAdd(&cD, 1);
            if (p < CMAX) { sIdxD[p] = Fdim; sValD[p] = 0.0f; }
        }
        if (0.0f <= tauE) {
            int p = atomicAdd(&cE, 1);
            if (p < CMAX) { sIdxE[p] = Fdim; sValE[p] = 0.0f; }
        }
    }
    __syncthreads();

    // ---- output: thread j = column, gather candidate W rows ----
    const int j = tid;
    const bool fullD = (cD > CMAX), fullE = (cE > CMAX);
    const int nD = fullD ? 0 : cD;
    const int nE = fullE ? 0 : cE;

    float accD = -CUDART_INF_F;
    float accE =  CUDART_INF_F;
    for (int i = 0; i < nD; ++i)
        accD = fmaxf(accD, sValD[i] + D[(size_t)sIdxD[i] * NW + j]);
    for (int i = 0; i < nE; ++i)
        accE = fminf(accE, sValE[i] - E[(size_t)sIdxE[i] * NW + j]);

    if (fullD) {                         // exact fallback (never expected)
        for (int k = 0; k < Fdim; ++k)
            accD = fmaxf(accD, sx[k] + D[(size_t)k * NW + j]);
        accD = fmaxf(accD, D[(size_t)Fdim * NW + j]);
    }
    if (fullE) {
        for (int k = 0; k < Fdim; ++k)
            accE = fminf(accE, sx[k] - E[(size_t)k * NW + j]);
        accE = fminf(accE, -E[(size_t)Fdim * NW + j]);
    }

    out[(size_t)b * OUTC + j]      = accE;   // eroded
    out[(size_t)b * OUTC + NW + j] = accD;   // dilated
}

extern "C" void kernel_launch(void* const* d_in, const int* in_sizes, int n_in,
                              void* d_out, int out_size)
{
    const float* x   = (const float*)d_in[0];   // (1024, 1024)
    const float* dil = (const float*)d_in[1];   // (1025, 256)
    const float* ero = (const float*)d_in[2];   // (1025, 256)
    float* out = (float*)d_out;                 // (1024, 512) = [eroded | dilated]

    k_wext<<<NB1, 256>>>(dil, ero);
    k_fused<<<B, 256>>>(x, dil, ero, out);
}

// round 11
// speedup vs baseline: 8.4286x; 1.1429x over previous
#include <cuda_runtime.h>
#include <math_constants.h>

// DilateErode via candidate pruning (exact).
//   dilated[b,n] = max_k ( xb_k + D[k,n] ),  eroded[b,n] = min_k ( xb_k - E[k,n] )
// xb = [x, 0]. Only k with xb_k >= rowMax - (maxD-minD)  (dilation) or
// xb_k <= rowMin + (maxE-minE)  (erosion) can win -> ~1-4 candidates/row.
// K1: weight extremes (512-block partials).
// K2: fused per-row kernel, 128 threads/block so the whole 1024-block grid is
//     co-resident in ONE wave (chain-latency hiding). Redundant tau fold in
//     every thread removes the serial thread-0 tail + one barrier.
// Exact: candidate superset + order-invariance of fp max/min. Full-scan
// fallback if a row ever exceeds CMAX candidates.

#define B     1024
#define Fdim  1024
#define NW    256
#define OUTC  512
#define WE4   ((Fdim + 1) * NW / 4)   // 65600 float4 per weight matrix
#define NB1   512
#define CMAX  64
#define T2    128                     // k_fused block size

__device__ float4 g_part[NB1];   // {maxD, minD, maxE, minE} per K1 block

// ---------------- K1: weight extremes, one pass, MLP=2 ----------------
__global__ __launch_bounds__(256)
void k_wext(const float* __restrict__ D, const float* __restrict__ E)
{
    const int i = blockIdx.x * 256 + threadIdx.x;
    float maxD = -CUDART_INF_F, minD = CUDART_INF_F;
    float maxE = -CUDART_INF_F, minE = CUDART_INF_F;
    if (i < WE4) {
        float4 d = ((const float4*)D)[i];
        float4 e = ((const float4*)E)[i];
        maxD = fmaxf(fmaxf(d.x, d.y), fmaxf(d.z, d.w));
        minD = fminf(fminf(d.x, d.y), fminf(d.z, d.w));
        maxE = fmaxf(fmaxf(e.x, e.y), fmaxf(e.z, e.w));
        minE = fminf(fminf(e.x, e.y), fminf(e.z, e.w));
    }
#pragma unroll
    for (int off = 16; off; off >>= 1) {
        maxD = fmaxf(maxD, __shfl_xor_sync(0xffffffffu, maxD, off));
        minD = fminf(minD, __shfl_xor_sync(0xffffffffu, minD, off));
        maxE = fmaxf(maxE, __shfl_xor_sync(0xffffffffu, maxE, off));
        minE = fminf(minE, __shfl_xor_sync(0xffffffffu, minE, off));
    }
    __shared__ float4 s[8];
    const int wid = threadIdx.x >> 5, lane = threadIdx.x & 31;
    if (lane == 0) s[wid] = make_float4(maxD, minD, maxE, minE);
    __syncthreads();
    if (wid == 0) {
        float4 r = s[lane & 7];
        float a = r.x, bm = r.y, c = r.z, dm = r.w;
#pragma unroll
        for (int off = 4; off; off >>= 1) {
            a  = fmaxf(a,  __shfl_xor_sync(0xffffffffu, a,  off));
            bm = fminf(bm, __shfl_xor_sync(0xffffffffu, bm, off));
            c  = fmaxf(c,  __shfl_xor_sync(0xffffffffu, c,  off));
            dm = fminf(dm, __shfl_xor_sync(0xffffffffu, dm, off));
        }
        if (lane == 0) g_part[blockIdx.x] = make_float4(a, bm, c, dm);
    }
}

// ------------- K2: fused row extremes + candidates + output -------------
__global__ __launch_bounds__(T2)
void k_fused(const float* __restrict__ x,
             const float* __restrict__ D,
             const float* __restrict__ E,
             float* __restrict__ out)
{
    const int b = blockIdx.x, tid = threadIdx.x;
    const int wid = tid >> 5, lane = tid & 31;

    __shared__ float sx[Fdim];                 // x row (fallback only)
    __shared__ float red[6][4];                // per-warp partials
    __shared__ int   cD, cE;
    __shared__ int   sIdxD[CMAX], sIdxE[CMAX];
    __shared__ float sValD[CMAX], sValE[CMAX];

    // front-load all independent globals (MLP = 6)
    const float4* xr = (const float4*)(x + (size_t)b * Fdim);
    float4 v0 = xr[tid];
    float4 v1 = xr[tid + T2];
    float4 p0 = g_part[tid];
    float4 p1 = g_part[tid + 128];
    float4 p2 = g_part[tid + 256];
    float4 p3 = g_part[tid + 384];

    ((float4*)sx)[tid]      = v0;
    ((float4*)sx)[tid + T2] = v1;
    if (tid == 0) { cD = 0; cE = 0; }

    float maxD = fmaxf(fmaxf(p0.x, p1.x), fmaxf(p2.x, p3.x));
    float minD = fminf(fminf(p0.y, p1.y), fminf(p2.y, p3.y));
    float maxE = fmaxf(fmaxf(p0.z, p1.z), fmaxf(p2.z, p3.z));
    float minE = fminf(fminf(p0.w, p1.w), fminf(p2.w, p3.w));
    float mx = fmaxf(fmaxf(fmaxf(v0.x, v0.y), fmaxf(v0.z, v0.w)),
                     fmaxf(fmaxf(v1.x, v1.y), fmaxf(v1.z, v1.w)));
    float mn = fminf(fminf(fminf(v0.x, v0.y), fminf(v0.z, v0.w)),
                     fminf(fminf(v1.x, v1.y), fminf(v1.z, v1.w)));

#pragma unroll
    for (int off = 16; off; off >>= 1) {
        mx   = fmaxf(mx,   __shfl_xor_sync(0xffffffffu, mx,   off));
        mn   = fminf(mn,   __shfl_xor_sync(0xffffffffu, mn,   off));
        maxD = fmaxf(maxD, __shfl_xor_sync(0xffffffffu, maxD, off));
        minD = fminf(minD, __shfl_xor_sync(0xffffffffu, minD, off));
        maxE = fmaxf(maxE, __shfl_xor_sync(0xffffffffu, maxE, off));
        minE = fminf(minE, __shfl_xor_sync(0xffffffffu, minE, off));
    }
    if (lane == 0) {
        red[0][wid] = mx;   red[1][wid] = mn;
        red[2][wid] = maxD; red[3][wid] = minD;
        red[4][wid] = maxE; red[5][wid] = minE;
    }
    __syncthreads();

    // every thread folds the 4 warp partials itself (no serial tail, no 2nd barrier)
    float MX = 0.0f, MN = 0.0f;          // bias feature xb = 0 included
    float MD = -CUDART_INF_F, mD = CUDART_INF_F;
    float ME = -CUDART_INF_F, mE = CUDART_INF_F;
#pragma unroll
    for (int w = 0; w < 4; ++w) {
        MX = fmaxf(MX, red[0][w]); MN = fminf(MN, red[1][w]);
        MD = fmaxf(MD, red[2][w]); mD = fminf(mD, red[3][w]);
        ME = fmaxf(ME, red[4][w]); mE = fminf(mE, red[5][w]);
    }
    const float tauD = MX - ((MD - mD) * 1.001f + 1e-6f);
    const float tauE = MN + ((ME - mE) * 1.001f + 1e-6f);

    // ---- candidate build (smem only): 8 x-values per thread ----
    float vv[8] = {v0.x, v0.y, v0.z, v0.w, v1.x, v1.y, v1.z, v1.w};
#pragma unroll
    for (int d = 0; d < 8; ++d) {
        const int k = (d < 4) ? (tid * 4 + d) : ((tid + T2) * 4 + (d - 4));
        const float xv = vv[d];
        if (xv >= tauD) {
            int p = atomicAdd(&cD, 1);
            if (p < CMAX) { sIdxD[p] = k; sValD[p] = xv; }
        }
        if (xv <= tauE) {
            int p = atomicAdd(&cE, 1);
            if (p < CMAX) { sIdxE[p] = k; sValE[p] = xv; }
        }
    }
    if (tid == 0) {                      // bias feature k = Fdim, value 0
        if (0.0f >= tauD) {
            int p = atomicAdd(&cD, 1);
            if (p < CMAX) { sIdxD[p] = Fdim; sValD[p] = 0.0f; }
        }
        if (0.0f <= tauE) {
            int p = atomicAdd(&cE, 1);
            if (p < CMAX) { sIdxE[p] = Fdim; sValE[p] = 0.0f; }
        }
    }
    __syncthreads();

    // ---- output: thread handles columns (2*tid, 2*tid+1) as float2 ----
    const bool fullD = (cD > CMAX), fullE = (cE > CMAX);
    const int nD = fullD ? 0 : cD;
    const int nE = fullE ? 0 : cE;

    float2 accD = make_float2(-CUDART_INF_F, -CUDART_INF_F);
    float2 accE = make_float2( CUDART_INF_F,  CUDART_INF_F);
    for (int i = 0; i < nD; ++i) {
        float2 w = ((const float2*)(D + (size_t)sIdxD[i] * NW))[tid];
        float xv = sValD[i];
        accD.x = fmaxf(accD.x, xv + w.x);
        accD.y = fmaxf(accD.y, xv + w.y);
    }
    for (int i = 0; i < nE; ++i) {
        float2 w = ((const float2*)(E + (size_t)sIdxE[i] * NW))[tid];
        float xv = sValE[i];
        accE.x = fminf(accE.x, xv - w.x);
        accE.y = fminf(accE.y, xv - w.y);
    }

    if (fullD) {                         // exact fallback (never expected)
        for (int k = 0; k < Fdim; ++k) {
            float2 w = ((const float2*)(D + (size_t)k * NW))[tid];
            accD.x = fmaxf(accD.x, sx[k] + w.x);
            accD.y = fmaxf(accD.y, sx[k] + w.y);
        }
        float2 w = ((const float2*)(D + (size_t)Fdim * NW))[tid];
        accD.x = fmaxf(accD.x, w.x);
        accD.y = fmaxf(accD.y, w.y);
    }
    if (fullE) {
        for (int k = 0; k < Fdim; ++k) {
            float2 w = ((const float2*)(E + (size_t)k * NW))[tid];
            accE.x = fminf(accE.x, sx[k] - w.x);
            accE.y = fminf(accE.y, sx[k] - w.y);
        }
        float2 w = ((const float2*)(E + (size_t)Fdim * NW))[tid];
        accE.x = fminf(accE.x, -w.x);
        accE.y = fminf(accE.y, -w.y);
    }

    float2* o = (float2*)(out + (size_t)b * OUTC);
    o[tid]            = accE;            // eroded  cols 2*tid..+1
    o[tid + T2]       = accD;            // dilated cols 2*tid..+1 (offset 256)
}

extern "C" void kernel_launch(void* const* d_in, const int* in_sizes, int n_in,
                              void* d_out, int out_size)
{
    const float* x   = (const float*)d_in[0];   // (1024, 1024)
    const float* dil = (const float*)d_in[1];   // (1025, 256)
    const float* ero = (const float*)d_in[2];   // (1025, 256)
    float* out = (float*)d_out;                 // (1024, 512) = [eroded | dilated]

    k_wext<<<NB1, 256>>>(dil, ero);
    k_fused<<<B, T2>>>(x, dil, ero, out);
}